// round 4
// baseline (speedup 1.0000x reference)
#include <cuda_runtime.h>

#define RFN 512
#define TN  32
#define KN  32
#define LN  2048
#define BK  32
#define NTILE (LN / BK)      // 64
#define STAGES 4
#define THREADS 128          // 2 branches x 64 threads -> 4 warps -> all 4 SMSPs

// Packed double fp32 FMA (Blackwell FFMA2) — only reachable via PTX fma.rn.f32x2.
__device__ __forceinline__ unsigned long long ffma2(unsigned long long a,
                                                    unsigned long long b,
                                                    unsigned long long c) {
    unsigned long long d;
    asm volatile("fma.rn.f32x2 %0, %1, %2, %3;" : "=l"(d) : "l"(a), "l"(b), "l"(c));
    return d;
}

__device__ __forceinline__ void cp_async16(unsigned dst, const float* src) {
    asm volatile("cp.async.cg.shared.global [%0], [%1], 16;" :: "r"(dst), "l"(src) : "memory");
}

// 16B-chunk XOR swizzle: chunk (row, c4) lives at column (c4 ^ (row & 7)).
#define SWZ(row, c4) ((c4) ^ ((row) & 7))

__global__ __launch_bounds__(THREADS)
void spyke_kernel(const float* __restrict__ rec,   // (T=32, C=1, RF=512, L=2048)
                  const float* __restrict__ Wt,    // (RF=512, K=32, C=1, L=2048)
                  float* __restrict__ out)         // (T, 1, K, RF)
{
    __shared__ __align__(16) float As[2][STAGES][TN][BK];   // [grp][stage][t][l] swizzled
    __shared__ __align__(16) float Bs[2][STAGES][KN][BK];   // [grp][stage][k][l] swizzled
    __shared__ float thr_s[2][TN][KN + 1];
    __shared__ unsigned mask_s[2];

    const int tid = threadIdx.x;
    const int grp = tid >> 6;          // branch within CTA (0/1)
    const int g   = tid & 63;          // thread within branch group
    const int rg  = g >> 3;            // t rows {rg, rg+8, rg+16, rg+24}
    const int cg  = g & 7;             // k cols {cg, cg+8, cg+16, cg+24}
    const int r   = blockIdx.x * 2 + grp;

    const float* Abase = rec + (size_t)r * LN;          // + t*512*2048 per row
    const float* Bbase = Wt  + (size_t)r * KN * LN;     // + k*2048 per row

    const unsigned sA = (unsigned)__cvta_generic_to_shared(&As[grp][0][0][0]);
    const unsigned sB = (unsigned)__cvta_generic_to_shared(&Bs[grp][0][0][0]);
    const unsigned STGB = TN * BK * 4;  // 4096 bytes per stage

    unsigned long long acc[4][4];
#pragma unroll
    for (int j = 0; j < 4; j++)
#pragma unroll
        for (int c = 0; c < 4; c++) acc[j][c] = 0ull;

    // ---- prologue: prefetch tiles 0..STAGES-2 ----
#pragma unroll
    for (int s = 0; s < STAGES - 1; s++) {
        const unsigned off = (unsigned)s * STGB;
        const int l0 = s * BK;
#pragma unroll
        for (int i = 0; i < 4; i++) {
            int f = i * 64 + g;
            int row = f >> 3, c4 = f & 7;
            unsigned soff = off + (unsigned)((row * BK + SWZ(row, c4) * 4) * 4);
            cp_async16(sA + soff, Abase + (size_t)row * (512 * 2048) + l0 + c4 * 4);
            cp_async16(sB + soff, Bbase + (size_t)row * LN + l0 + c4 * 4);
        }
        asm volatile("cp.async.commit_group;" ::: "memory");
    }

    for (int ti = 0; ti < NTILE; ti++) {
        // tile ti arrived once <= STAGES-2 groups pending
        asm volatile("cp.async.wait_group %0;" :: "n"(STAGES - 2) : "memory");
        __syncthreads();   // data visible; all warps past compute(ti-1)

        // prefetch tile ti+STAGES-1 into stage (ti+STAGES-1)%STAGES == (ti-1)%STAGES
        if (ti + STAGES - 1 < NTILE) {
            const int tn = ti + STAGES - 1;
            const unsigned off = (unsigned)(tn & (STAGES - 1)) * STGB;
            const int l0 = tn * BK;
#pragma unroll
            for (int i = 0; i < 4; i++) {
                int f = i * 64 + g;
                int row = f >> 3, c4 = f & 7;
                unsigned soff = off + (unsigned)((row * BK + SWZ(row, c4) * 4) * 4);
                cp_async16(sA + soff, Abase + (size_t)row * (512 * 2048) + l0 + c4 * 4);
                cp_async16(sB + soff, Bbase + (size_t)row * LN + l0 + c4 * 4);
            }
        }
        asm volatile("cp.async.commit_group;" ::: "memory");

        // ---- compute tile ti ----
        const int buf = ti & (STAGES - 1);
#pragma unroll
        for (int lc4 = 0; lc4 < BK / 4; lc4++) {
            ulonglong2 av[4], bv[4];
            const int scA = (lc4 ^ rg) * 4;   // A rows all have row&7 == rg
            const int scB = (lc4 ^ cg) * 4;   // B rows all have row&7 == cg
#pragma unroll
            for (int j = 0; j < 4; j++)
                av[j] = *(const ulonglong2*)&As[grp][buf][rg + 8 * j][scA];
#pragma unroll
            for (int c = 0; c < 4; c++)
                bv[c] = *(const ulonglong2*)&Bs[grp][buf][cg + 8 * c][scB];
#pragma unroll
            for (int j = 0; j < 4; j++)
#pragma unroll
                for (int c = 0; c < 4; c++) {
                    acc[j][c] = ffma2(av[j].x, bv[c].x, acc[j][c]);
                    acc[j][c] = ffma2(av[j].y, bv[c].y, acc[j][c]);
                }
        }
    }

    // ---- epilogue: threshold, store thr to smem ----
    float thrv[4][4];
#pragma unroll
    for (int j = 0; j < 4; j++)
#pragma unroll
        for (int c = 0; c < 4; c++) {
            unsigned long long a = acc[j][c];
            float lo = __uint_as_float((unsigned)(a & 0xffffffffull));
            float hi = __uint_as_float((unsigned)(a >> 32));
            float pot = lo + hi;
            float tv  = (pot > 20.0f) ? pot : 0.0f;
            thrv[j][c] = tv;
            thr_s[grp][rg + 8 * j][cg + 8 * c] = tv;
        }
    __syncthreads();

    // ---- kWTA winner mask (warp 0 of each group; lane = feature k) ----
    if (g < 32) {
        const int lane = g;
        int cnt = 0;
#pragma unroll
        for (int t = 0; t < TN; t++) cnt += (thr_s[grp][t][lane] > 0.0f) ? 1 : 0;
        int first = 32 - cnt;
        if (first > 31) first = 31;          // cnt==0 -> 31 ; cnt>=1 -> 0..31
        float vals = thr_s[grp][first][lane];
        float vk = (cnt > 0) ? vals : 0.0f;
        float vmax = vk;
#pragma unroll
        for (int o = 16; o > 0; o >>= 1) {
            float ov = __shfl_xor_sync(0xffffffffu, vmax, o);
            vmax = (ov > vmax) ? ov : vmax;
        }
        const float v = vmax * 32.0f;
        const float total = (float)cnt * (vals + v);

        float cur = total;
        bool win = false;
#pragma unroll
        for (int it = 0; it < 4; it++) {
            float bvv = cur;
            int bi = lane;
#pragma unroll
            for (int o = 16; o > 0; o >>= 1) {
                float ov = __shfl_xor_sync(0xffffffffu, bvv, o);
                int   oi = __shfl_xor_sync(0xffffffffu, bi, o);
                if (ov > bvv || (ov == bvv && oi < bi)) { bvv = ov; bi = oi; }
            }
            if (lane == bi) {
                if (cur > 0.0f) win = true;  // valid = top_val != 0
                cur = -1.0f;                 // exclude from later rounds
            }
        }
        unsigned m = __ballot_sync(0xffffffffu, win);
        if (lane == 0) mask_s[grp] = m;
    }
    __syncthreads();

    // ---- write output: out[t,0,k,r] = (thr>0 && k is winner) ? 1 : 0 ----
    const unsigned m = mask_s[grp];
#pragma unroll
    for (int j = 0; j < 4; j++)
#pragma unroll
        for (int c = 0; c < 4; c++) {
            int t = rg + 8 * j;
            int k = cg + 8 * c;
            out[(size_t)t * (KN * RFN) + (size_t)k * RFN + r] =
                (thrv[j][c] > 0.0f && ((m >> k) & 1u)) ? 1.0f : 0.0f;
        }
}

extern "C" void kernel_launch(void* const* d_in, const int* in_sizes, int n_in,
                              void* d_out, int out_size) {
    const float* rec = (const float*)d_in[0];   // rec_field (32,1,512,2048)
    const float* Wt  = (const float*)d_in[1];   // W (512,32,1,2048)
    // d_in[2] = reward — unused by the reference output
    float* out = (float*)d_out;                 // (32,1,32,512)
    spyke_kernel<<<RFN / 2, THREADS>>>(rec, Wt, out);
}

// round 5
// speedup vs baseline: 1.1170x; 1.1170x over previous
#include <cuda_runtime.h>

#define RFN 512
#define TN  32
#define KN  32
#define LN  2048
#define BK  32
#define NTILE (LN / BK)      // 64
#define STAGES 4
#define THREADS 32           // one warp == one branch; fully warp-private

// Packed double fp32 FMA (Blackwell FFMA2) — only reachable via PTX fma.rn.f32x2.
__device__ __forceinline__ unsigned long long ffma2(unsigned long long a,
                                                    unsigned long long b,
                                                    unsigned long long c) {
    unsigned long long d;
    asm volatile("fma.rn.f32x2 %0, %1, %2, %3;" : "=l"(d) : "l"(a), "l"(b), "l"(c));
    return d;
}

__device__ __forceinline__ void cp_async16(unsigned dst, const float* src) {
    asm volatile("cp.async.cg.shared.global [%0], [%1], 16;" :: "r"(dst), "l"(src) : "memory");
}

// 16B-chunk XOR swizzle: chunk (row, c4) lives at column (c4 ^ (row & 7)).
#define SWZ(row, c4) ((c4) ^ ((row) & 7))

__global__ __launch_bounds__(THREADS)
void spyke_kernel(const float* __restrict__ rec,   // (T=32, C=1, RF=512, L=2048)
                  const float* __restrict__ Wt,    // (RF=512, K=32, C=1, L=2048)
                  float* __restrict__ out)         // (T, 1, K, RF)
{
    __shared__ __align__(16) float As[STAGES][TN][BK];   // swizzled chunks
    __shared__ __align__(16) float Bs[STAGES][KN][BK];
    __shared__ float thr_s[TN][KN + 1];

    const int lane = threadIdx.x;      // 0..31
    const int rg = lane >> 2;          // 0..7 -> t rows {rg, rg+8, rg+16, rg+24}
    const int cg = lane & 3;           // 0..3 -> k cols {cg, cg+4, ..., cg+28}
    const int r  = blockIdx.x;

    const float* Abase = rec + (size_t)r * LN;          // + t*512*2048 per row
    const float* Bbase = Wt  + (size_t)r * KN * LN;     // + k*2048 per row

    const unsigned sA = (unsigned)__cvta_generic_to_shared(&As[0][0][0]);
    const unsigned sB = (unsigned)__cvta_generic_to_shared(&Bs[0][0][0]);
    const unsigned STGB = TN * BK * 4;  // 4096 bytes per stage

    // acc[j][c]: output (t = rg+8j, k = cg+4c); (even-l, odd-l) packed f32x2
    unsigned long long acc[4][8];
#pragma unroll
    for (int j = 0; j < 4; j++)
#pragma unroll
        for (int c = 0; c < 8; c++) acc[j][c] = 0ull;

    // ---- prologue: prefetch tiles 0..STAGES-2 (warp loads all 512 chunks) ----
#pragma unroll
    for (int s = 0; s < STAGES - 1; s++) {
        const unsigned off = (unsigned)s * STGB;
        const int l0 = s * BK;
#pragma unroll
        for (int i = 0; i < 16; i++) {
            int idx = (i & 7) * 32 + lane;        // chunk index within A or B
            int row = idx >> 3, c4 = idx & 7;
            unsigned soff = off + (unsigned)((row * BK + SWZ(row, c4) * 4) * 4);
            if (i < 8)
                cp_async16(sA + soff, Abase + (size_t)row * (512 * 2048) + l0 + c4 * 4);
            else
                cp_async16(sB + soff, Bbase + (size_t)row * LN + l0 + c4 * 4);
        }
        asm volatile("cp.async.commit_group;" ::: "memory");
    }

    for (int ti = 0; ti < NTILE; ti++) {
        asm volatile("cp.async.wait_group %0;" :: "n"(STAGES - 2) : "memory");
        __syncwarp();   // warp-private pipeline: warp-scope fence is enough

        // prefetch tile ti+STAGES-1 into stage (ti-1)%STAGES
        if (ti + STAGES - 1 < NTILE) {
            const int tn = ti + STAGES - 1;
            const unsigned off = (unsigned)(tn & (STAGES - 1)) * STGB;
            const int l0 = tn * BK;
#pragma unroll
            for (int i = 0; i < 16; i++) {
                int idx = (i & 7) * 32 + lane;
                int row = idx >> 3, c4 = idx & 7;
                unsigned soff = off + (unsigned)((row * BK + SWZ(row, c4) * 4) * 4);
                if (i < 8)
                    cp_async16(sA + soff, Abase + (size_t)row * (512 * 2048) + l0 + c4 * 4);
                else
                    cp_async16(sB + soff, Bbase + (size_t)row * LN + l0 + c4 * 4);
            }
        }
        asm volatile("cp.async.commit_group;" ::: "memory");

        // ---- compute tile ti ----
        const int buf = ti & (STAGES - 1);
#pragma unroll
        for (int lc4 = 0; lc4 < BK / 4; lc4++) {
            ulonglong2 av[4], bv[8];
#pragma unroll
            for (int j = 0; j < 4; j++) {
                const int row = rg + 8 * j;               // row&7 == rg
                av[j] = *(const ulonglong2*)&As[buf][row][(lc4 ^ rg) * 4];
            }
#pragma unroll
            for (int c = 0; c < 8; c++) {
                const int row = cg + 4 * c;
                bv[c] = *(const ulonglong2*)&Bs[buf][row][(lc4 ^ (row & 7)) * 4];
            }
#pragma unroll
            for (int j = 0; j < 4; j++)
#pragma unroll
                for (int c = 0; c < 8; c++) {
                    acc[j][c] = ffma2(av[j].x, bv[c].x, acc[j][c]);
                    acc[j][c] = ffma2(av[j].y, bv[c].y, acc[j][c]);
                }
        }
    }

    // ---- epilogue: threshold, store thr to smem ----
    float thrv[4][8];
#pragma unroll
    for (int j = 0; j < 4; j++)
#pragma unroll
        for (int c = 0; c < 8; c++) {
            unsigned long long a = acc[j][c];
            float lo = __uint_as_float((unsigned)(a & 0xffffffffull));
            float hi = __uint_as_float((unsigned)(a >> 32));
            float pot = lo + hi;
            float tv  = (pot > 20.0f) ? pot : 0.0f;
            thrv[j][c] = tv;
            thr_s[rg + 8 * j][cg + 4 * c] = tv;
        }
    __syncwarp();

    // ---- kWTA winner mask (lane = feature k) ----
    unsigned m;
    {
        int cnt = 0;
#pragma unroll
        for (int t = 0; t < TN; t++) cnt += (thr_s[t][lane] > 0.0f) ? 1 : 0;
        int first = 32 - cnt;
        if (first > 31) first = 31;          // cnt==0 -> 31 ; cnt>=1 -> 0..31
        float vals = thr_s[first][lane];
        float vk = (cnt > 0) ? vals : 0.0f;
        float vmax = vk;
#pragma unroll
        for (int o = 16; o > 0; o >>= 1) {
            float ov = __shfl_xor_sync(0xffffffffu, vmax, o);
            vmax = (ov > vmax) ? ov : vmax;
        }
        const float v = vmax * 32.0f;
        const float total = (float)cnt * (vals + v);

        float cur = total;
        bool win = false;
#pragma unroll
        for (int it = 0; it < 4; it++) {
            float bvv = cur;
            int bi = lane;
#pragma unroll
            for (int o = 16; o > 0; o >>= 1) {
                float ov = __shfl_xor_sync(0xffffffffu, bvv, o);
                int   oi = __shfl_xor_sync(0xffffffffu, bi, o);
                if (ov > bvv || (ov == bvv && oi < bi)) { bvv = ov; bi = oi; }
            }
            if (lane == bi) {
                if (cur > 0.0f) win = true;  // valid = top_val != 0
                cur = -1.0f;                 // exclude from later rounds
            }
        }
        m = __ballot_sync(0xffffffffu, win);
    }

    // ---- write output: out[t,0,k,r] = (thr>0 && k is winner) ? 1 : 0 ----
#pragma unroll
    for (int j = 0; j < 4; j++)
#pragma unroll
        for (int c = 0; c < 8; c++) {
            int t = rg + 8 * j;
            int k = cg + 4 * c;
            out[(size_t)t * (KN * RFN) + (size_t)k * RFN + r] =
                (thrv[j][c] > 0.0f && ((m >> k) & 1u)) ? 1.0f : 0.0f;
        }
}

extern "C" void kernel_launch(void* const* d_in, const int* in_sizes, int n_in,
                              void* d_out, int out_size) {
    const float* rec = (const float*)d_in[0];   // rec_field (32,1,512,2048)
    const float* Wt  = (const float*)d_in[1];   // W (512,32,1,2048)
    // d_in[2] = reward — unused by the reference output
    float* out = (float*)d_out;                 // (32,1,32,512)
    spyke_kernel<<<RFN, THREADS>>>(rec, Wt, out);
}